// round 3
// baseline (speedup 1.0000x reference)
#include <cuda_runtime.h>
#include <math.h>

// ---------------------------------------------------------------------------
// Problem dims (compile-time)
// ---------------------------------------------------------------------------
#define B_     32
#define S_     512
#define DM     512         // d_model
#define NH     8
#define DK     64
#define NL     4           // blocks
#define DFF    2048
#define FEAT   2048
#define NTOK   (B_ * S_)   // 16384

// ---------------------------------------------------------------------------
// Scratch (device globals — no cudaMalloc allowed)
// ---------------------------------------------------------------------------
__device__ float g_h   [NTOK * DM];     // 32 MB
__device__ float g_q   [NTOK * DM];
__device__ float g_k   [NTOK * DM];
__device__ float g_v   [NTOK * DM];
__device__ float g_ctx [NTOK * DM];
__device__ float g_tmp [NTOK * DM];
__device__ float g_ff  [NTOK * DFF];    // 128 MB
__device__ float g_pool[B_ * DM];

// ---------------------------------------------------------------------------
// Positional encoding helper (matches reference fp32 math)
// ---------------------------------------------------------------------------
__device__ __forceinline__ float pe_arg(int s, int c_even) {
    const float kPE = (float)(-9.210340371976184 / 512.0);   // -ln(1e4)/d_model
    return (float)s * expf((float)c_even * kPE);
}

// ---------------------------------------------------------------------------
// SGEMM: C[M,N] = A[M,K] @ W[K,N] + bias, with epilogue variants
//   EPI 0: bias only
//   EPI 1: bias + relu
//   EPI 2: bias + positional encoding (row -> (b,s))
//   EPI 3: bias + residual (res[M,N])
// Tiles: BM=128, BN=64, BK=16; 256 threads; 8x4 per thread.
// Requires M%128==0, N%64==0, K%16==0 (true for all calls here).
// ---------------------------------------------------------------------------
template<int EPI>
__global__ __launch_bounds__(256)
void gemm_kernel(const float* __restrict__ A, const float* __restrict__ W,
                 const float* __restrict__ bias, const float* __restrict__ res,
                 float* __restrict__ C, int M, int N, int K)
{
    __shared__ float As[16 * 132];   // [k][m], padded stride 132
    __shared__ float Bs[16 * 64];    // [k][n]

    const int t  = threadIdx.x;
    const int tx = t & 15;
    const int ty = t >> 4;
    const int m0 = blockIdx.y << 7;
    const int n0 = blockIdx.x << 6;

    float acc[8][4];
#pragma unroll
    for (int i = 0; i < 8; i++)
#pragma unroll
        for (int j = 0; j < 4; j++) acc[i][j] = 0.0f;

    const int arow = t >> 2;             // 0..63
    const int akq  = (t & 3) << 2;       // 0,4,8,12
    const int bkr  = t >> 4;             // 0..15
    const int bnc  = (t & 15) << 2;      // 0..60

    const float* Ap0 = A + (size_t)(m0 + arow)      * K + akq;
    const float* Ap1 = A + (size_t)(m0 + arow + 64) * K + akq;
    const float* Wp  = W + (size_t)bkr * N + n0 + bnc;

    for (int k0 = 0; k0 < K; k0 += 16) {
        float4 a0 = *(const float4*)(Ap0 + k0);
        float4 a1 = *(const float4*)(Ap1 + k0);
        float4 bb = *(const float4*)(Wp + (size_t)k0 * N);

        As[(akq + 0) * 132 + arow] = a0.x;
        As[(akq + 1) * 132 + arow] = a0.y;
        As[(akq + 2) * 132 + arow] = a0.z;
        As[(akq + 3) * 132 + arow] = a0.w;
        As[(akq + 0) * 132 + arow + 64] = a1.x;
        As[(akq + 1) * 132 + arow + 64] = a1.y;
        As[(akq + 2) * 132 + arow + 64] = a1.z;
        As[(akq + 3) * 132 + arow + 64] = a1.w;
        *(float4*)(Bs + (bkr << 6) + bnc) = bb;
        __syncthreads();

#pragma unroll
        for (int k = 0; k < 16; k++) {
            float4 av0 = *(const float4*)(As + k * 132 + (ty << 3));
            float4 av1 = *(const float4*)(As + k * 132 + (ty << 3) + 4);
            float4 bv  = *(const float4*)(Bs + (k << 6) + (tx << 2));
            float ar[8] = {av0.x, av0.y, av0.z, av0.w, av1.x, av1.y, av1.z, av1.w};
            float br[4] = {bv.x, bv.y, bv.z, bv.w};
#pragma unroll
            for (int i = 0; i < 8; i++)
#pragma unroll
                for (int j = 0; j < 4; j++)
                    acc[i][j] = fmaf(ar[i], br[j], acc[i][j]);
        }
        __syncthreads();
    }

    // epilogue
    const int col = n0 + (tx << 2);
    float4 bv = *(const float4*)(bias + col);
#pragma unroll
    for (int i = 0; i < 8; i++) {
        int row = m0 + (ty << 3) + i;
        float4 o;
        o.x = acc[i][0] + bv.x;
        o.y = acc[i][1] + bv.y;
        o.z = acc[i][2] + bv.z;
        o.w = acc[i][3] + bv.w;
        if (EPI == 1) {
            o.x = fmaxf(o.x, 0.0f); o.y = fmaxf(o.y, 0.0f);
            o.z = fmaxf(o.z, 0.0f); o.w = fmaxf(o.w, 0.0f);
        }
        if (EPI == 2) {
            int s  = row & (S_ - 1);
            float a0 = pe_arg(s, col);
            float a1 = pe_arg(s, col + 2);
            o.x += sinf(a0); o.y += cosf(a0);
            o.z += sinf(a1); o.w += cosf(a1);
        }
        if (EPI == 3) {
            float4 r = *(const float4*)(res + (size_t)row * N + col);
            o.x += r.x; o.y += r.y; o.z += r.z; o.w += r.w;
        }
        *(float4*)(C + (size_t)row * N + col) = o;
    }
}

// ---------------------------------------------------------------------------
// Fused attention: per (b, h, 64-query tile), flash-style online softmax.
// blockDim 256 (16x16), per-thread 4x4. Dynamic smem: Qs,Ks,Vs,Ps [64][68].
// ---------------------------------------------------------------------------
__global__ __launch_bounds__(256)
void attn_kernel(const float* __restrict__ q, const float* __restrict__ k,
                 const float* __restrict__ v, float* __restrict__ ctx)
{
    extern __shared__ float sm[];
    float* Qs = sm;                 // [d*68 + r]  (pre-scaled)
    float* Ks = sm + 64 * 68;       // [d*68 + c]
    float* Vs = sm + 2 * 64 * 68;   // [r*68 + d]
    float* Ps = sm + 3 * 64 * 68;   // [c*68 + r]

    const int t  = threadIdx.x;
    const int tx = t & 15;
    const int ty = t >> 4;
    const int bh = blockIdx.y;
    const int b  = bh >> 3;
    const int h  = bh & 7;
    const int hoff = h << 6;
    const size_t btok0 = (size_t)b * S_;
    const size_t qtok0 = btok0 + ((size_t)blockIdx.x << 6);

    // load Q tile, pre-scaled by 1/sqrt(dk)
#pragma unroll
    for (int u = 0; u < 4; u++) {
        int idx = t + (u << 8);
        int r   = idx >> 4;
        int dq  = (idx & 15) << 2;
        float4 val = *(const float4*)&q[(qtok0 + r) * DM + hoff + dq];
        Qs[(dq + 0) * 68 + r] = val.x * 0.125f;
        Qs[(dq + 1) * 68 + r] = val.y * 0.125f;
        Qs[(dq + 2) * 68 + r] = val.z * 0.125f;
        Qs[(dq + 3) * 68 + r] = val.w * 0.125f;
    }

    float m[4], l[4], o[4][4];
#pragma unroll
    for (int i = 0; i < 4; i++) {
        m[i] = -INFINITY; l[i] = 0.0f;
#pragma unroll
        for (int j = 0; j < 4; j++) o[i][j] = 0.0f;
    }

    for (int kt0 = 0; kt0 < S_; kt0 += 64) {
        __syncthreads();   // protect Ks/Vs/Ps reuse (and Qs on first iter)
#pragma unroll
        for (int u = 0; u < 4; u++) {
            int idx = t + (u << 8);
            int r   = idx >> 4;
            int dq  = (idx & 15) << 2;
            float4 kv = *(const float4*)&k[(btok0 + kt0 + r) * DM + hoff + dq];
            Ks[(dq + 0) * 68 + r] = kv.x;
            Ks[(dq + 1) * 68 + r] = kv.y;
            Ks[(dq + 2) * 68 + r] = kv.z;
            Ks[(dq + 3) * 68 + r] = kv.w;
            float4 vv = *(const float4*)&v[(btok0 + kt0 + r) * DM + hoff + dq];
            *(float4*)&Vs[r * 68 + dq] = vv;
        }
        __syncthreads();

        // S tile: p[i][j] = sum_d Qs[d][ty*4+i] * Ks[d][tx*4+j]
        float p[4][4];
#pragma unroll
        for (int i = 0; i < 4; i++)
#pragma unroll
            for (int j = 0; j < 4; j++) p[i][j] = 0.0f;

#pragma unroll 8
        for (int d = 0; d < 64; d++) {
            float4 qa = *(const float4*)&Qs[d * 68 + (ty << 2)];
            float4 ka = *(const float4*)&Ks[d * 68 + (tx << 2)];
            float qr[4] = {qa.x, qa.y, qa.z, qa.w};
            float kr[4] = {ka.x, ka.y, ka.z, ka.w};
#pragma unroll
            for (int i = 0; i < 4; i++)
#pragma unroll
                for (int j = 0; j < 4; j++)
                    p[i][j] = fmaf(qr[i], kr[j], p[i][j]);
        }

        // online softmax (row = ty*4+i, spread across the 16 tx threads)
#pragma unroll
        for (int i = 0; i < 4; i++) {
            float rm = fmaxf(fmaxf(p[i][0], p[i][1]), fmaxf(p[i][2], p[i][3]));
#pragma unroll
            for (int off = 1; off < 16; off <<= 1)
                rm = fmaxf(rm, __shfl_xor_sync(0xffffffffu, rm, off, 16));
            float mn   = fmaxf(m[i], rm);
            float corr = expf(m[i] - mn);
            m[i] = mn;
            float rs = 0.0f;
#pragma unroll
            for (int j = 0; j < 4; j++) {
                p[i][j] = expf(p[i][j] - mn);
                rs += p[i][j];
            }
#pragma unroll
            for (int off = 1; off < 16; off <<= 1)
                rs += __shfl_xor_sync(0xffffffffu, rs, off, 16);
            l[i] = l[i] * corr + rs;
#pragma unroll
            for (int j = 0; j < 4; j++) o[i][j] *= corr;
        }

        // stage P transposed: Ps[c][r]
#pragma unroll
        for (int i = 0; i < 4; i++)
#pragma unroll
            for (int j = 0; j < 4; j++)
                Ps[((tx << 2) + j) * 68 + (ty << 2) + i] = p[i][j];
        __syncthreads();

        // O += P @ V : o[i][j] over (row=ty*4+i, dim=tx*4+j)
#pragma unroll 8
        for (int kt = 0; kt < 64; kt++) {
            float4 pa = *(const float4*)&Ps[kt * 68 + (ty << 2)];
            float4 va = *(const float4*)&Vs[kt * 68 + (tx << 2)];
            float pr[4] = {pa.x, pa.y, pa.z, pa.w};
            float vr[4] = {va.x, va.y, va.z, va.w};
#pragma unroll
            for (int i = 0; i < 4; i++)
#pragma unroll
                for (int j = 0; j < 4; j++)
                    o[i][j] = fmaf(pr[i], vr[j], o[i][j]);
        }
    }

    // normalize and write ctx (layout [token][h*64 + d])
#pragma unroll
    for (int i = 0; i < 4; i++) {
        float inv = 1.0f / l[i];
        float4 r;
        r.x = o[i][0] * inv; r.y = o[i][1] * inv;
        r.z = o[i][2] * inv; r.w = o[i][3] * inv;
        *(float4*)&ctx[(qtok0 + (ty << 2) + i) * DM + hoff + (tx << 2)] = r;
    }
}

// ---------------------------------------------------------------------------
// Block reduction helper
// ---------------------------------------------------------------------------
__device__ __forceinline__ float block_sum(float v, float* red, int nwarps)
{
    int lane = threadIdx.x & 31, w = threadIdx.x >> 5;
#pragma unroll
    for (int off = 16; off > 0; off >>= 1)
        v += __shfl_xor_sync(0xffffffffu, v, off);
    if (lane == 0) red[w] = v;
    __syncthreads();
    if (w == 0) {
        float tsum = (lane < nwarps) ? red[lane] : 0.0f;
#pragma unroll
        for (int off = 16; off > 0; off >>= 1)
            tsum += __shfl_xor_sync(0xffffffffu, tsum, off);
        if (lane == 0) red[0] = tsum;
    }
    __syncthreads();
    float r = red[0];
    __syncthreads();
    return r;
}

// ---------------------------------------------------------------------------
// LayerNorm over D=512 (in already contains residual). One block per row.
// ---------------------------------------------------------------------------
__global__ __launch_bounds__(128)
void ln_kernel(const float* __restrict__ in, const float* __restrict__ g,
               const float* __restrict__ bb, float* __restrict__ out)
{
    __shared__ float red[32];
    size_t row = blockIdx.x;
    int c = threadIdx.x << 2;
    float4 x = *(const float4*)&in[row * DM + c];
    float mu  = block_sum(x.x + x.y + x.z + x.w, red, 4) * (1.0f / DM);
    float dx = x.x - mu, dy = x.y - mu, dz = x.z - mu, dw = x.w - mu;
    float var = block_sum(dx * dx + dy * dy + dz * dz + dw * dw, red, 4) * (1.0f / DM);
    float rstd = rsqrtf(var + 1e-5f);
    float4 gv = *(const float4*)&g[c];
    float4 bv = *(const float4*)&bb[c];
    float4 o;
    o.x = dx * rstd * gv.x + bv.x;
    o.y = dy * rstd * gv.y + bv.y;
    o.z = dz * rstd * gv.z + bv.z;
    o.w = dw * rstd * gv.w + bv.w;
    *(float4*)&out[row * DM + c] = o;
}

// ---------------------------------------------------------------------------
// Mean pool over sequence: pooled[b][d] = mean_s h[b,s,d]
// ---------------------------------------------------------------------------
__global__ __launch_bounds__(512)
void pool_kernel(const float* __restrict__ h, float* __restrict__ pooled)
{
    int b = blockIdx.x, d = threadIdx.x;
    const float* p = h + (size_t)b * S_ * DM + d;
    float s = 0.0f;
#pragma unroll 8
    for (int i = 0; i < S_; i++) s += p[(size_t)i * DM];
    pooled[b * DM + d] = s * (1.0f / S_);
}

// ---------------------------------------------------------------------------
// Final: LN(pooled) @ fcw + fcb -> sigmoid
// ---------------------------------------------------------------------------
__global__ __launch_bounds__(512)
void final_kernel(const float* __restrict__ pooled, const float* __restrict__ lng,
                  const float* __restrict__ lnb, const float* __restrict__ fcw,
                  const float* __restrict__ fcb, float* __restrict__ out)
{
    __shared__ float red[32];
    int b = blockIdx.x, d = threadIdx.x;
    float x = pooled[b * DM + d];
    float mu  = block_sum(x, red, 16) * (1.0f / DM);
    float dx  = x - mu;
    float var = block_sum(dx * dx, red, 16) * (1.0f / DM);
    float y = dx * rsqrtf(var + 1e-5f) * lng[d] + lnb[d];
    float z = block_sum(y * fcw[d], red, 16);
    if (d == 0) out[b] = 1.0f / (1.0f + expf(-(z + fcb[0])));
}

// ---------------------------------------------------------------------------
// Launch
// ---------------------------------------------------------------------------
extern "C" void kernel_launch(void* const* d_in, const int* in_sizes, int n_in,
                              void* d_out, int out_size)
{
    const float* x    = (const float*)d_in[0];
    const float* Wp   = (const float*)d_in[1];
    const float* bp   = (const float*)d_in[2];
    const float* Wq   = (const float*)d_in[3];
    const float* bq   = (const float*)d_in[4];
    const float* Wk   = (const float*)d_in[5];
    const float* bk   = (const float*)d_in[6];
    const float* Wv   = (const float*)d_in[7];
    const float* bv   = (const float*)d_in[8];
    const float* Wo   = (const float*)d_in[9];
    const float* bo   = (const float*)d_in[10];
    const float* ln1g = (const float*)d_in[11];
    const float* ln1b = (const float*)d_in[12];
    const float* W1   = (const float*)d_in[13];
    const float* b1   = (const float*)d_in[14];
    const float* W2   = (const float*)d_in[15];
    const float* b2   = (const float*)d_in[16];
    const float* ln2g = (const float*)d_in[17];
    const float* ln2b = (const float*)d_in[18];
    const float* lng  = (const float*)d_in[19];
    const float* lnb  = (const float*)d_in[20];
    const float* fcw  = (const float*)d_in[21];
    const float* fcb  = (const float*)d_in[22];
    float* out = (float*)d_out;

    float *h, *q, *k, *v, *ctx, *tmp, *ff, *pooled;
    cudaGetSymbolAddress((void**)&h,      g_h);
    cudaGetSymbolAddress((void**)&q,      g_q);
    cudaGetSymbolAddress((void**)&k,      g_k);
    cudaGetSymbolAddress((void**)&v,      g_v);
    cudaGetSymbolAddress((void**)&ctx,    g_ctx);
    cudaGetSymbolAddress((void**)&tmp,    g_tmp);
    cudaGetSymbolAddress((void**)&ff,     g_ff);
    cudaGetSymbolAddress((void**)&pooled, g_pool);

    const int ATTN_SMEM = 4 * 64 * 68 * (int)sizeof(float);   // 69632 B
    cudaFuncSetAttribute(attn_kernel,
                         cudaFuncAttributeMaxDynamicSharedMemorySize, ATTN_SMEM);

    dim3 gDM (DM  / 64, NTOK / 128);   // N=512 GEMMs
    dim3 gFF (DFF / 64, NTOK / 128);   // N=2048 GEMM
    dim3 gAtt(S_ / 64, B_ * NH);

    // input projection + positional encoding
    gemm_kernel<2><<<gDM, 256>>>(x, Wp, bp, nullptr, h, NTOK, DM, FEAT);

    for (int l = 0; l < NL; l++) {
        const float* Wq_l = Wq + (size_t)l * DM * DM;
        const float* Wk_l = Wk + (size_t)l * DM * DM;
        const float* Wv_l = Wv + (size_t)l * DM * DM;
        const float* Wo_l = Wo + (size_t)l * DM * DM;
        const float* W1_l = W1 + (size_t)l * DM * DFF;
        const float* W2_l = W2 + (size_t)l * DFF * DM;

        gemm_kernel<0><<<gDM, 256>>>(h, Wq_l, bq + l * DM, nullptr, q, NTOK, DM, DM);
        gemm_kernel<0><<<gDM, 256>>>(h, Wk_l, bk + l * DM, nullptr, k, NTOK, DM, DM);
        gemm_kernel<0><<<gDM, 256>>>(h, Wv_l, bv + l * DM, nullptr, v, NTOK, DM, DM);

        attn_kernel<<<gAtt, 256, ATTN_SMEM>>>(q, k, v, ctx);

        // attn_out + residual -> tmp ; LN -> h
        gemm_kernel<3><<<gDM, 256>>>(ctx, Wo_l, bo + l * DM, h, tmp, NTOK, DM, DM);
        ln_kernel<<<NTOK, 128>>>(tmp, ln1g + l * DM, ln1b + l * DM, h);

        // FFN
        gemm_kernel<1><<<gFF, 256>>>(h, W1_l, b1 + l * DFF, nullptr, ff, NTOK, DFF, DM);
        gemm_kernel<3><<<gDM, 256>>>(ff, W2_l, b2 + l * DM, h, tmp, NTOK, DM, DFF);
        ln_kernel<<<NTOK, 128>>>(tmp, ln2g + l * DM, ln2b + l * DM, h);
    }

    pool_kernel<<<B_, 512>>>(h, pooled);
    final_kernel<<<B_, 512>>>(pooled, lng, lnb, fcw, fcb, out);
}